// round 3
// baseline (speedup 1.0000x reference)
#include <cuda_runtime.h>
#include <math.h>

// Problem constants
#define Bz 4
#define Sq 2048
#define Cc 2048
#define Dd 512
#define QKVO (3 * Dd)   // 1536

// GEMM tiling
#define BM 128
#define BN 128
#define BK 16
#define TM 8
#define TN 8
#define PADS 4

// Scratch (static device memory; allocation-free per harness rules)
__device__ float g_qkv[(size_t)Bz * Sq * QKVO];    // [b, s, 1536] (q|k|v)
__device__ float g_attn[(size_t)Bz * Sq * Sq];     // [b, q, k]
__device__ float g_ctx[(size_t)Bz * Sq * Dd];      // [b, s, d]

// ---------------------------------------------------------------------------
// Generic tiled fp32 GEMM:
//   C[m,n] = alpha * sum_k A[m,k] * B(k,n) (+ bias[n])
//   TRANS_B:  B(k,n) = B[n*ldb + k]   (NT: both operands K-contiguous)
//   !TRANS_B: B(k,n) = B[k*ldb + n]   (NN)
// grid = (N/BN, M/BM, batch); all dims multiples of tile sizes.
// ---------------------------------------------------------------------------
template <bool TRANS_B, bool HAS_BIAS>
__global__ void __launch_bounds__(256)
gemm_kernel(const float* __restrict__ A, int lda, long sA,
            const float* __restrict__ B, int ldb, long sB,
            float* __restrict__ C, int ldc, long sC,
            int K, const float* __restrict__ bias, float alpha)
{
    __shared__ float As[BK][BM + PADS];
    __shared__ float Bs[BK][BN + PADS];

    A += (long)blockIdx.z * sA;
    B += (long)blockIdx.z * sB;
    C += (long)blockIdx.z * sC;

    const int m0 = blockIdx.y * BM;
    const int n0 = blockIdx.x * BN;
    const int tid = threadIdx.x;

    // loader indices (K-contiguous tiles, 128 rows x 16 cols)
    const int ar = tid >> 2;          // 0..63
    const int ac = (tid & 3) << 2;    // 0,4,8,12
    // NN B loader (16 rows x 128 cols)
    const int bkr = tid >> 5;         // 0..7
    const int bnc = (tid & 31) << 2;  // 0..124

    // compute thread layout
    const int ty = tid >> 4;          // 0..15
    const int tx = tid & 15;          // 0..15

    float acc[TM][TN];
#pragma unroll
    for (int i = 0; i < TM; i++)
#pragma unroll
        for (int j = 0; j < TN; j++) acc[i][j] = 0.0f;

    float4 pa0, pa1, pb0, pb1;

    // initial stage load
    {
        const float* Ap = A + (long)(m0 + ar) * lda + ac;
        pa0 = *(const float4*)(Ap);
        pa1 = *(const float4*)(Ap + (long)64 * lda);
        if (TRANS_B) {
            const float* Bp = B + (long)(n0 + ar) * ldb + ac;
            pb0 = *(const float4*)(Bp);
            pb1 = *(const float4*)(Bp + (long)64 * ldb);
        } else {
            const float* Bp = B + (long)bkr * ldb + n0 + bnc;
            pb0 = *(const float4*)(Bp);
            pb1 = *(const float4*)(Bp + (long)8 * ldb);
        }
    }

    int k0 = 0;
    for (;;) {
        // commit staged registers to smem
        As[ac + 0][ar] = pa0.x; As[ac + 1][ar] = pa0.y;
        As[ac + 2][ar] = pa0.z; As[ac + 3][ar] = pa0.w;
        As[ac + 0][ar + 64] = pa1.x; As[ac + 1][ar + 64] = pa1.y;
        As[ac + 2][ar + 64] = pa1.z; As[ac + 3][ar + 64] = pa1.w;
        if (TRANS_B) {
            Bs[ac + 0][ar] = pb0.x; Bs[ac + 1][ar] = pb0.y;
            Bs[ac + 2][ar] = pb0.z; Bs[ac + 3][ar] = pb0.w;
            Bs[ac + 0][ar + 64] = pb1.x; Bs[ac + 1][ar + 64] = pb1.y;
            Bs[ac + 2][ar + 64] = pb1.z; Bs[ac + 3][ar + 64] = pb1.w;
        } else {
            *(float4*)&Bs[bkr][bnc]     = pb0;
            *(float4*)&Bs[bkr + 8][bnc] = pb1;
        }
        __syncthreads();

        k0 += BK;
        const bool more = (k0 < K);
        if (more) {  // prefetch next tile while computing current
            const float* Ap = A + (long)(m0 + ar) * lda + k0 + ac;
            pa0 = *(const float4*)(Ap);
            pa1 = *(const float4*)(Ap + (long)64 * lda);
            if (TRANS_B) {
                const float* Bp = B + (long)(n0 + ar) * ldb + k0 + ac;
                pb0 = *(const float4*)(Bp);
                pb1 = *(const float4*)(Bp + (long)64 * ldb);
            } else {
                const float* Bp = B + (long)k0 * ldb + (long)bkr * ldb + n0 + bnc;
                pb0 = *(const float4*)(Bp);
                pb1 = *(const float4*)(Bp + (long)8 * ldb);
            }
        }

#pragma unroll
        for (int k = 0; k < BK; k++) {
            float a[TM], b[TN];
            *(float4*)&a[0] = *(const float4*)&As[k][ty * TM];
            *(float4*)&a[4] = *(const float4*)&As[k][ty * TM + 4];
            *(float4*)&b[0] = *(const float4*)&Bs[k][tx * TN];
            *(float4*)&b[4] = *(const float4*)&Bs[k][tx * TN + 4];
#pragma unroll
            for (int i = 0; i < TM; i++)
#pragma unroll
                for (int j = 0; j < TN; j++)
                    acc[i][j] = fmaf(a[i], b[j], acc[i][j]);
        }

        if (!more) break;
        __syncthreads();
    }

    // epilogue
    float bv[TN];
#pragma unroll
    for (int j = 0; j < TN; j++)
        bv[j] = HAS_BIAS ? bias[n0 + tx * TN + j] : 0.0f;

#pragma unroll
    for (int i = 0; i < TM; i++) {
        const long row = (long)(m0 + ty * TM + i) * ldc + n0 + tx * TN;
        float4 o0, o1;
        o0.x = alpha * acc[i][0] + bv[0];
        o0.y = alpha * acc[i][1] + bv[1];
        o0.z = alpha * acc[i][2] + bv[2];
        o0.w = alpha * acc[i][3] + bv[3];
        o1.x = alpha * acc[i][4] + bv[4];
        o1.y = alpha * acc[i][5] + bv[5];
        o1.z = alpha * acc[i][6] + bv[6];
        o1.w = alpha * acc[i][7] + bv[7];
        *(float4*)&C[row]     = o0;
        *(float4*)&C[row + 4] = o1;
    }
}

// ---------------------------------------------------------------------------
// Row softmax over 2048 columns; one block (256 threads) per row.
// ---------------------------------------------------------------------------
__global__ void __launch_bounds__(256)
softmax_kernel(float* __restrict__ attn)
{
    __shared__ float red[256];
    float* p = attn + (long)blockIdx.x * Sq;
    const int tid = threadIdx.x;

    float v[8];
    float m = -1e30f;
#pragma unroll
    for (int i = 0; i < 8; i++) {
        v[i] = p[i * 256 + tid];
        m = fmaxf(m, v[i]);
    }
    red[tid] = m;
    __syncthreads();
#pragma unroll
    for (int s = 128; s > 0; s >>= 1) {
        if (tid < s) red[tid] = fmaxf(red[tid], red[tid + s]);
        __syncthreads();
    }
    m = red[0];
    __syncthreads();

    float sum = 0.0f;
#pragma unroll
    for (int i = 0; i < 8; i++) {
        v[i] = expf(v[i] - m);
        sum += v[i];
    }
    red[tid] = sum;
    __syncthreads();
#pragma unroll
    for (int s = 128; s > 0; s >>= 1) {
        if (tid < s) red[tid] += red[tid + s];
        __syncthreads();
    }
    const float inv = 1.0f / red[0];
#pragma unroll
    for (int i = 0; i < 8; i++)
        p[i * 256 + tid] = v[i] * inv;
}

// ---------------------------------------------------------------------------
extern "C" void kernel_launch(void* const* d_in, const int* in_sizes, int n_in,
                              void* d_out, int out_size)
{
    const float* x    = (const float*)d_in[0];  // [4, 2048, 2048]
    const float* Wqkv = (const float*)d_in[1];  // [1536, 2048]
    const float* bqkv = (const float*)d_in[2];  // [1536]
    const float* Wo   = (const float*)d_in[3];  // [2048, 512]
    const float* bo   = (const float*)d_in[4];  // [2048]
    float* out = (float*)d_out;                 // [4, 2048, 2048]

    float *qkv, *attn, *ctx;
    cudaGetSymbolAddress((void**)&qkv,  g_qkv);
    cudaGetSymbolAddress((void**)&attn, g_attn);
    cudaGetSymbolAddress((void**)&ctx,  g_ctx);

    const dim3 blk(256);
    const float inv_sqrt_d = 1.0f / sqrtf((float)Dd);

    // 1) QKV projection: [8192,2048] x Wqkv^T[2048,1536] + bqkv -> qkv
    gemm_kernel<true, true><<<dim3(QKVO / BN, (Bz * Sq) / BM, 1), blk>>>(
        x, Cc, 0L, Wqkv, Cc, 0L, qkv, QKVO, 0L, Cc, bqkv, 1.0f);

    // 2) attn = Q K^T * (1/sqrt(d)); per batch
    gemm_kernel<true, false><<<dim3(Sq / BN, Sq / BM, Bz), blk>>>(
        qkv, QKVO, (long)Sq * QKVO,
        qkv + Dd, QKVO, (long)Sq * QKVO,
        attn, Sq, (long)Sq * Sq,
        Dd, nullptr, inv_sqrt_d);

    // 3) softmax over key axis
    softmax_kernel<<<Bz * Sq, blk>>>(attn);

    // 4) ctx = P V ; per batch (NN)
    gemm_kernel<false, false><<<dim3(Dd / BN, Sq / BM, Bz), blk>>>(
        attn, Sq, (long)Sq * Sq,
        qkv + 2 * Dd, QKVO, (long)Sq * QKVO,
        ctx, Dd, (long)Sq * Dd,
        Sq, nullptr, 1.0f);

    // 5) out = ctx Wo^T + bo
    gemm_kernel<true, true><<<dim3(Cc / BN, (Bz * Sq) / BM, 1), blk>>>(
        ctx, Dd, 0L, Wo, Dd, 0L, out, Cc, 0L, Dd, bo, 1.0f);
}

// round 5
// speedup vs baseline: 2.8206x; 2.8206x over previous
#include <cuda_runtime.h>
#include <math.h>
#include <stdint.h>

// Problem constants
#define Bz 4
#define Sq 2048
#define Cc 2048
#define Dd 512
#define QKVO (3 * Dd)   // 1536

// Scratch (static device memory; allocation-free per harness rules)
__device__ float g_qkv[(size_t)Bz * Sq * QKVO];    // [b, s, 1536] (q|k|v)
__device__ float g_attn[(size_t)Bz * Sq * Sq];     // [b, q, k]
__device__ float g_ctx[(size_t)Bz * Sq * Dd];      // [b, s, d]
__device__ float g_vt[(size_t)Bz * Dd * Sq];       // [b, d, k]  (V transposed)

// ---------------------------------------------------------------------------
// PTX helpers (sm_80-era ISA — safe on plain sm_103 target)
// ---------------------------------------------------------------------------
__device__ __forceinline__ uint32_t smem_u32(const void* p) {
    uint32_t a;
    asm("{ .reg .u64 t; cvta.to.shared.u64 t, %1; cvt.u32.u64 %0, t; }"
        : "=r"(a) : "l"(p));
    return a;
}

#define CP_ASYNC16(dst_u32, src_ptr) \
    asm volatile("cp.async.cg.shared.global [%0], [%1], 16;" \
                 :: "r"(dst_u32), "l"(src_ptr))
#define CP_COMMIT() asm volatile("cp.async.commit_group;" ::: "memory")
#define CP_WAIT(n)  asm volatile("cp.async.wait_group %0;" :: "n"(n) : "memory")

__device__ __forceinline__ uint32_t f2tf32(float f) {
    uint32_t r;
    asm("cvt.rna.tf32.f32 %0, %1;" : "=r"(r) : "f"(f));
    return r;
}

__device__ __forceinline__ void mma_tf32(float& c0, float& c1, float& c2, float& c3,
                                         uint32_t a0, uint32_t a1, uint32_t a2, uint32_t a3,
                                         uint32_t b0, uint32_t b1) {
    asm volatile(
        "mma.sync.aligned.m16n8k8.row.col.f32.tf32.tf32.f32 "
        "{%0,%1,%2,%3}, {%4,%5,%6,%7}, {%8,%9}, {%0,%1,%2,%3};"
        : "+f"(c0), "+f"(c1), "+f"(c2), "+f"(c3)
        : "r"(a0), "r"(a1), "r"(a2), "r"(a3), "r"(b0), "r"(b1));
}

// ---------------------------------------------------------------------------
// tf32 tensor-core NT GEMM:
//   C[m,n] = alpha * sum_k A[m*lda+k] * B[n*ldb+k] (+ bias[n])
// CTA tile 128x128, BK=16, 256 threads = 8 warps in 2(M)x4(N), warp tile 64x32.
// All dims multiples of tiles. cp.async 2-stage double buffer.
// ---------------------------------------------------------------------------
#define BK 16
#define LDS_STRIDE 20   // 16 + 4 pad floats -> conflict-free fragment loads

template <bool HAS_BIAS>
__global__ void __launch_bounds__(256)
mma_gemm_nt(const float* __restrict__ A, int lda, long sA,
            const float* __restrict__ B, int ldb, long sB,
            float* __restrict__ C, int ldc, long sC,
            int K, const float* __restrict__ bias, float alpha)
{
    __shared__ float As[2][128][LDS_STRIDE];
    __shared__ float Bs[2][128][LDS_STRIDE];

    A += (long)blockIdx.z * sA;
    B += (long)blockIdx.z * sB;
    C += (long)blockIdx.z * sC;
    const int m0 = blockIdx.y * 128;
    const int n0 = blockIdx.x * 128;

    const int tid = threadIdx.x;
    const int lane = tid & 31;
    const int warp = tid >> 5;
    const int wm = warp >> 2;        // 0..1  -> warp M offset wm*64
    const int wn = warp & 3;         // 0..3  -> warp N offset wn*32
    const int grp = lane >> 2;       // 0..7
    const int tig = lane & 3;        // 0..3

    const uint32_t sA0 = smem_u32(&As[0][0][0]);
    const uint32_t sB0 = smem_u32(&Bs[0][0][0]);
    const uint32_t stage_bytes = 128 * LDS_STRIDE * 4;

    // loader: 512 16B-chunks per operand per tile; 2 chunks/thread/operand
    const int ch0 = tid;             // chunk ids tid, tid+256
    const int r0c = ch0 >> 2, c0c = ch0 & 3;
    const int ch1 = tid + 256;
    const int r1c = ch1 >> 2, c1c = ch1 & 3;

    auto load_tile = [&](int t, int p) {
        const int k0 = t * BK;
        CP_ASYNC16(sA0 + p * stage_bytes + (r0c * LDS_STRIDE + c0c * 4) * 4,
                   A + (long)(m0 + r0c) * lda + k0 + c0c * 4);
        CP_ASYNC16(sA0 + p * stage_bytes + (r1c * LDS_STRIDE + c1c * 4) * 4,
                   A + (long)(m0 + r1c) * lda + k0 + c1c * 4);
        CP_ASYNC16(sB0 + p * stage_bytes + (r0c * LDS_STRIDE + c0c * 4) * 4,
                   B + (long)(n0 + r0c) * ldb + k0 + c0c * 4);
        CP_ASYNC16(sB0 + p * stage_bytes + (r1c * LDS_STRIDE + c1c * 4) * 4,
                   B + (long)(n0 + r1c) * ldb + k0 + c1c * 4);
        CP_COMMIT();
    };

    float acc[4][4][4];
#pragma unroll
    for (int i = 0; i < 4; i++)
#pragma unroll
        for (int j = 0; j < 4; j++)
#pragma unroll
            for (int r = 0; r < 4; r++) acc[i][j][r] = 0.0f;

    const int KT = K / BK;
    load_tile(0, 0);

    for (int t = 0; t < KT; t++) {
        const int p = t & 1;
        if (t + 1 < KT) {
            load_tile(t + 1, p ^ 1);
            CP_WAIT(1);
        } else {
            CP_WAIT(0);
        }
        __syncthreads();

#pragma unroll
        for (int kk = 0; kk < 2; kk++) {
            const int kb = kk * 8;
            uint32_t af[4][4], bf[4][2];
#pragma unroll
            for (int i = 0; i < 4; i++) {
                const int mr = wm * 64 + i * 16 + grp;
                af[i][0] = f2tf32(As[p][mr][kb + tig]);
                af[i][1] = f2tf32(As[p][mr + 8][kb + tig]);
                af[i][2] = f2tf32(As[p][mr][kb + tig + 4]);
                af[i][3] = f2tf32(As[p][mr + 8][kb + tig + 4]);
            }
#pragma unroll
            for (int j = 0; j < 4; j++) {
                const int nr = wn * 32 + j * 8 + grp;
                bf[j][0] = f2tf32(Bs[p][nr][kb + tig]);
                bf[j][1] = f2tf32(Bs[p][nr][kb + tig + 4]);
            }
#pragma unroll
            for (int i = 0; i < 4; i++)
#pragma unroll
                for (int j = 0; j < 4; j++)
                    mma_tf32(acc[i][j][0], acc[i][j][1], acc[i][j][2], acc[i][j][3],
                             af[i][0], af[i][1], af[i][2], af[i][3],
                             bf[j][0], bf[j][1]);
        }
        __syncthreads();
    }

    // epilogue: each thread owns (i: 4 m-tiles)x(j: 4 n-tiles), regs map:
    //   c0: (row=grp,      col=2*tig), c1: col+1
    //   c2: (row=grp+8,    col=2*tig), c3: col+1
#pragma unroll
    for (int j = 0; j < 4; j++) {
        const int n = n0 + wn * 32 + j * 8 + tig * 2;
        float b0 = 0.f, b1 = 0.f;
        if (HAS_BIAS) { b0 = bias[n]; b1 = bias[n + 1]; }
#pragma unroll
        for (int i = 0; i < 4; i++) {
            const int m = m0 + wm * 64 + i * 16 + grp;
            float2 v0, v1;
            v0.x = alpha * acc[i][j][0] + b0;
            v0.y = alpha * acc[i][j][1] + b1;
            v1.x = alpha * acc[i][j][2] + b0;
            v1.y = alpha * acc[i][j][3] + b1;
            *(float2*)(C + (long)m * ldc + n) = v0;
            *(float2*)(C + (long)(m + 8) * ldc + n) = v1;
        }
    }
}

// ---------------------------------------------------------------------------
// V transpose: Vt[b][d][k] = qkv[b][k][1024 + d]   (makes PV an NT GEMM)
// ---------------------------------------------------------------------------
__global__ void __launch_bounds__(256)
transpose_v(const float* __restrict__ qkv, float* __restrict__ vt)
{
    __shared__ float t[32][33];
    const int b = blockIdx.z;
    const int k0 = blockIdx.x * 32;
    const int d0 = blockIdx.y * 32;
    const float* src = qkv + (long)b * Sq * QKVO + 2 * Dd;
    float* dst = vt + (long)b * Dd * Sq;
    const int x = threadIdx.x;       // 0..31
    const int y = threadIdx.y;       // 0..7
#pragma unroll
    for (int j = 0; j < 32; j += 8)
        t[y + j][x] = src[(long)(k0 + y + j) * QKVO + d0 + x];
    __syncthreads();
#pragma unroll
    for (int j = 0; j < 32; j += 8)
        dst[(long)(d0 + y + j) * Sq + k0 + x] = t[x][y + j];
}

// ---------------------------------------------------------------------------
// Row softmax over 2048 columns; one block (256 threads) per row.
// ---------------------------------------------------------------------------
__global__ void __launch_bounds__(256)
softmax_kernel(float* __restrict__ attn)
{
    __shared__ float red[256];
    float* p = attn + (long)blockIdx.x * Sq;
    const int tid = threadIdx.x;

    float v[8];
    float m = -1e30f;
#pragma unroll
    for (int i = 0; i < 8; i++) {
        v[i] = p[i * 256 + tid];
        m = fmaxf(m, v[i]);
    }
    red[tid] = m;
    __syncthreads();
#pragma unroll
    for (int s = 128; s > 0; s >>= 1) {
        if (tid < s) red[tid] = fmaxf(red[tid], red[tid + s]);
        __syncthreads();
    }
    m = red[0];
    __syncthreads();

    float sum = 0.0f;
#pragma unroll
    for (int i = 0; i < 8; i++) {
        v[i] = expf(v[i] - m);
        sum += v[i];
    }
    red[tid] = sum;
    __syncthreads();
#pragma unroll
    for (int s = 128; s > 0; s >>= 1) {
        if (tid < s) red[tid] += red[tid + s];
        __syncthreads();
    }
    const float inv = 1.0f / red[0];
#pragma unroll
    for (int i = 0; i < 8; i++)
        p[i * 256 + tid] = v[i] * inv;
}

// ---------------------------------------------------------------------------
extern "C" void kernel_launch(void* const* d_in, const int* in_sizes, int n_in,
                              void* d_out, int out_size)
{
    const float* x    = (const float*)d_in[0];  // [4, 2048, 2048]
    const float* Wqkv = (const float*)d_in[1];  // [1536, 2048]
    const float* bqkv = (const float*)d_in[2];  // [1536]
    const float* Wo   = (const float*)d_in[3];  // [2048, 512]
    const float* bo   = (const float*)d_in[4];  // [2048]
    float* out = (float*)d_out;                 // [4, 2048, 2048]

    float *qkv, *attn, *ctx, *vt;
    cudaGetSymbolAddress((void**)&qkv,  g_qkv);
    cudaGetSymbolAddress((void**)&attn, g_attn);
    cudaGetSymbolAddress((void**)&ctx,  g_ctx);
    cudaGetSymbolAddress((void**)&vt,   g_vt);

    const dim3 blk(256);
    const float inv_sqrt_d = 1.0f / sqrtf((float)Dd);

    // 1) QKV projection: [8192,2048] x Wqkv^T + bqkv -> qkv   (M=8192,N=1536,K=2048)
    mma_gemm_nt<true><<<dim3(QKVO / 128, (Bz * Sq) / 128, 1), blk>>>(
        x, Cc, 0L, Wqkv, Cc, 0L, qkv, QKVO, 0L, Cc, bqkv, 1.0f);

    // 1b) transpose V for NT PV gemm
    transpose_v<<<dim3(Sq / 32, Dd / 32, Bz), dim3(32, 8)>>>(qkv, vt);

    // 2) attn = Q K^T * (1/sqrt(d)); per batch   (M=2048,N=2048,K=512)
    mma_gemm_nt<false><<<dim3(Sq / 128, Sq / 128, Bz), blk>>>(
        qkv, QKVO, (long)Sq * QKVO,
        qkv + Dd, QKVO, (long)Sq * QKVO,
        attn, Sq, (long)Sq * Sq,
        Dd, nullptr, inv_sqrt_d);

    // 3) softmax over key axis
    softmax_kernel<<<Bz * Sq, blk>>>(attn);

    // 4) ctx = P V ; per batch, NT against Vt   (M=2048,N=512,K=2048)
    mma_gemm_nt<false><<<dim3(Dd / 128, Sq / 128, Bz), blk>>>(
        attn, Sq, (long)Sq * Sq,
        vt, Sq, (long)Dd * Sq,
        ctx, Dd, (long)Sq * Dd,
        Sq, nullptr, 1.0f);

    // 5) out = ctx Wo^T + bo   (M=8192,N=2048,K=512)
    mma_gemm_nt<true><<<dim3(Cc / 128, (Bz * Sq) / 128, 1), blk>>>(
        ctx, Dd, 0L, Wo, Dd, 0L, out, Cc, 0L, Dd, bo, 1.0f);
}

// round 6
// speedup vs baseline: 5.7896x; 2.0526x over previous
#include <cuda_runtime.h>
#include <cuda_fp16.h>
#include <math.h>
#include <stdint.h>

// Problem constants
#define Bz 4
#define Sq 2048
#define Cc 2048
#define Dd 512
#define QKVO (3 * Dd)   // 1536

// Scratch (static device memory; allocation-free per harness rules)
__device__ __align__(16) __half g_xh[(size_t)Bz * Sq * Cc];     // x in fp16
__device__ __align__(16) __half g_wqkv[(size_t)QKVO * Cc];      // Wqkv fp16
__device__ __align__(16) __half g_wo[(size_t)Cc * Dd];          // Wo fp16
__device__ __align__(16) __half g_qkv[(size_t)Bz * Sq * QKVO];  // q|k|v fp16
__device__ float  g_attn[(size_t)Bz * Sq * Sq];                 // logits fp32
__device__ __align__(16) __half g_p[(size_t)Bz * Sq * Sq];      // softmax P fp16
__device__ __align__(16) __half g_ctx[(size_t)Bz * Sq * Dd];    // ctx fp16
__device__ __align__(16) __half g_vt[(size_t)Bz * Dd * Sq];     // V^T fp16

// ---------------------------------------------------------------------------
// PTX helpers (sm_80-era ISA — safe on plain sm_103 target)
// ---------------------------------------------------------------------------
__device__ __forceinline__ uint32_t smem_u32(const void* p) {
    uint32_t a;
    asm("{ .reg .u64 t; cvta.to.shared.u64 t, %1; cvt.u32.u64 %0, t; }"
        : "=r"(a) : "l"(p));
    return a;
}

#define CP_ASYNC16(dst_u32, src_ptr) \
    asm volatile("cp.async.cg.shared.global [%0], [%1], 16;" \
                 :: "r"(dst_u32), "l"(src_ptr))
#define CP_COMMIT() asm volatile("cp.async.commit_group;" ::: "memory")
#define CP_WAIT(n)  asm volatile("cp.async.wait_group %0;" :: "n"(n) : "memory")

__device__ __forceinline__ uint32_t lds32(uint32_t a) {
    uint32_t v;
    asm("ld.shared.b32 %0, [%1];" : "=r"(v) : "r"(a));
    return v;
}

__device__ __forceinline__ void mma_f16(float& c0, float& c1, float& c2, float& c3,
                                        uint32_t a0, uint32_t a1, uint32_t a2, uint32_t a3,
                                        uint32_t b0, uint32_t b1) {
    asm volatile(
        "mma.sync.aligned.m16n8k16.row.col.f32.f16.f16.f32 "
        "{%0,%1,%2,%3}, {%4,%5,%6,%7}, {%8,%9}, {%0,%1,%2,%3};"
        : "+f"(c0), "+f"(c1), "+f"(c2), "+f"(c3)
        : "r"(a0), "r"(a1), "r"(a2), "r"(a3), "r"(b0), "r"(b1));
}

// ---------------------------------------------------------------------------
// fp16 tensor-core NT GEMM (fp32 accumulate):
//   C[m,n] = OutT( alpha * sum_k A[m*lda+k]*B[n*ldb+k] (+ bias[n]) )
// CTA tile 128x128, BK=32 halves, 256 threads = 8 warps (2M x 4N), warp 64x32.
// 3-stage cp.async pipeline. Rows are 64B in smem, 16B-chunk XOR swizzle:
//   phys_chunk = chunk ^ ((row>>1)&3)  -> conflict-free LDS fragment loads.
// All dims multiples of tiles.
// ---------------------------------------------------------------------------
#define BKH 32
#define STAGE_BYTES 16384           // 8KB A + 8KB B
#define GSMEM_BYTES (3 * STAGE_BYTES)

template <typename OutT, bool HAS_BIAS>
__global__ void __launch_bounds__(256, 2)
hgemm_nt(const __half* __restrict__ A, int lda, long sA,
         const __half* __restrict__ B, int ldb, long sB,
         OutT* __restrict__ C, int ldc, long sC,
         int K, const float* __restrict__ bias, float alpha)
{
    extern __shared__ char smem[];
    const uint32_t sbase = smem_u32(smem);

    A += (long)blockIdx.z * sA;
    B += (long)blockIdx.z * sB;
    C += (long)blockIdx.z * sC;
    const int m0 = blockIdx.y * 128;
    const int n0 = blockIdx.x * 128;

    const int tid = threadIdx.x;
    const int lane = tid & 31;
    const int warp = tid >> 5;
    const int wm = warp >> 2;        // 0..1  -> warp M offset wm*64
    const int wn = warp & 3;         // 0..3  -> warp N offset wn*32
    const int grp = lane >> 2;       // 0..7
    const int tig = lane & 3;        // 0..3

    // loader: per operand 512 chunks (128 rows x 4 x 16B); 2 chunks/thread
    const int lr = tid >> 2;                 // row 0..63 (second chunk +64)
    const int lc = tid & 3;                  // logical 16B chunk 0..3
    const uint32_t sw0 = (uint32_t)((lc ^ ((lr >> 1) & 3)) << 4);
    const uint32_t sw1 = (uint32_t)((lc ^ (((lr + 64) >> 1) & 3)) << 4);

    auto load_tile = [&](int t, int s) {
        const int k0 = t * BKH;
        const uint32_t sa = sbase + s * STAGE_BYTES;
        const uint32_t sb = sa + 8192;
        const __half* Ap = A + (long)(m0 + lr) * lda + k0 + lc * 8;
        const __half* Bp = B + (long)(n0 + lr) * ldb + k0 + lc * 8;
        CP_ASYNC16(sa + lr * 64 + sw0, Ap);
        CP_ASYNC16(sa + (lr + 64) * 64 + sw1, Ap + (long)64 * lda);
        CP_ASYNC16(sb + lr * 64 + sw0, Bp);
        CP_ASYNC16(sb + (lr + 64) * 64 + sw1, Bp + (long)64 * ldb);
        CP_COMMIT();
    };

    float acc[4][4][4];
#pragma unroll
    for (int i = 0; i < 4; i++)
#pragma unroll
        for (int j = 0; j < 4; j++)
#pragma unroll
            for (int r = 0; r < 4; r++) acc[i][j][r] = 0.0f;

    const int KT = K / BKH;
    load_tile(0, 0);
    load_tile(1, 1);

    // swizzle precompute for fragment loads: (mr>>1)&3 == (grp>>1)&3 since
    // the rest of mr is a multiple of 16 (and nr likewise a multiple of 8).
    const uint32_t fsw = (uint32_t)((grp >> 1) & 3);

    for (int t = 0; t < KT; t++) {
        const int p = t % 3;
        if (t + 1 < KT) { CP_WAIT(1); } else { CP_WAIT(0); }
        __syncthreads();
        if (t + 2 < KT) load_tile(t + 2, (t + 2) % 3);

        const uint32_t sa = sbase + p * STAGE_BYTES;
        const uint32_t sb = sa + 8192;

#pragma unroll
        for (int kk = 0; kk < 2; kk++) {
            const uint32_t ck0 = (uint32_t)(((kk * 2)     ^ fsw) << 4);
            const uint32_t ck1 = (uint32_t)(((kk * 2 + 1) ^ fsw) << 4);
            uint32_t af[4][4], bf[4][2];
#pragma unroll
            for (int i = 0; i < 4; i++) {
                const int mr = wm * 64 + i * 16 + grp;
                const uint32_t rb  = sa + mr * 64 + tig * 4;
                const uint32_t rb8 = rb + 8 * 64;
                af[i][0] = lds32(rb  + ck0);
                af[i][1] = lds32(rb8 + ck0);
                af[i][2] = lds32(rb  + ck1);
                af[i][3] = lds32(rb8 + ck1);
            }
#pragma unroll
            for (int j = 0; j < 4; j++) {
                const int nr = wn * 32 + j * 8 + grp;
                const uint32_t rb = sb + nr * 64 + tig * 4;
                bf[j][0] = lds32(rb + ck0);
                bf[j][1] = lds32(rb + ck1);
            }
#pragma unroll
            for (int i = 0; i < 4; i++)
#pragma unroll
                for (int j = 0; j < 4; j++)
                    mma_f16(acc[i][j][0], acc[i][j][1], acc[i][j][2], acc[i][j][3],
                            af[i][0], af[i][1], af[i][2], af[i][3],
                            bf[j][0], bf[j][1]);
        }
    }

    // epilogue: c0,c1 -> (row grp, cols 2tig,2tig+1); c2,c3 -> row grp+8
#pragma unroll
    for (int j = 0; j < 4; j++) {
        const int n = n0 + wn * 32 + j * 8 + tig * 2;
        float b0 = 0.f, b1 = 0.f;
        if (HAS_BIAS) { b0 = bias[n]; b1 = bias[n + 1]; }
#pragma unroll
        for (int i = 0; i < 4; i++) {
            const int m = m0 + wm * 64 + i * 16 + grp;
            const float v00 = alpha * acc[i][j][0] + b0;
            const float v01 = alpha * acc[i][j][1] + b1;
            const float v10 = alpha * acc[i][j][2] + b0;
            const float v11 = alpha * acc[i][j][3] + b1;
            if (sizeof(OutT) == 4) {
                *(float2*)((float*)C + (long)m * ldc + n) = make_float2(v00, v01);
                *(float2*)((float*)C + (long)(m + 8) * ldc + n) = make_float2(v10, v11);
            } else {
                *(__half2*)((__half*)C + (long)m * ldc + n) = __floats2half2_rn(v00, v01);
                *(__half2*)((__half*)C + (long)(m + 8) * ldc + n) = __floats2half2_rn(v10, v11);
            }
        }
    }
}

// ---------------------------------------------------------------------------
// fp32 -> fp16 conversion (n multiple of 8)
// ---------------------------------------------------------------------------
__global__ void __launch_bounds__(256)
f2h_kernel(const float* __restrict__ src, __half* __restrict__ dst, int n)
{
    const int i = (blockIdx.x * 256 + threadIdx.x) * 8;
    if (i >= n) return;
    const float4 a = *(const float4*)(src + i);
    const float4 b = *(const float4*)(src + i + 4);
    __half2 h[4];
    h[0] = __floats2half2_rn(a.x, a.y);
    h[1] = __floats2half2_rn(a.z, a.w);
    h[2] = __floats2half2_rn(b.x, b.y);
    h[3] = __floats2half2_rn(b.z, b.w);
    *(uint4*)(dst + i) = *(uint4*)h;
}

// ---------------------------------------------------------------------------
// V transpose (fp16): Vt[b][d][k] = qkv[b][k][1024 + d]
// ---------------------------------------------------------------------------
__global__ void __launch_bounds__(256)
transpose_v(const __half* __restrict__ qkv, __half* __restrict__ vt)
{
    __shared__ __half t[32][34];
    const int b = blockIdx.z;
    const int k0 = blockIdx.x * 32;
    const int d0 = blockIdx.y * 32;
    const __half* src = qkv + (long)b * Sq * QKVO + 2 * Dd;
    __half* dst = vt + (long)b * Dd * Sq;
    const int x = threadIdx.x;       // 0..31
    const int y = threadIdx.y;       // 0..7
#pragma unroll
    for (int j = 0; j < 32; j += 8)
        t[y + j][x] = src[(long)(k0 + y + j) * QKVO + d0 + x];
    __syncthreads();
#pragma unroll
    for (int j = 0; j < 32; j += 8)
        dst[(long)(d0 + y + j) * Sq + k0 + x] = t[x][y + j];
}

// ---------------------------------------------------------------------------
// Row softmax over 2048 fp32 logits -> fp16 probabilities.
// ---------------------------------------------------------------------------
__global__ void __launch_bounds__(256)
softmax_kernel(const float* __restrict__ attn, __half* __restrict__ prob)
{
    __shared__ float red[256];
    const float* p = attn + (long)blockIdx.x * Sq;
    __half* o = prob + (long)blockIdx.x * Sq;
    const int tid = threadIdx.x;

    float v[8];
    float m = -1e30f;
#pragma unroll
    for (int i = 0; i < 8; i++) {
        v[i] = p[i * 256 + tid];
        m = fmaxf(m, v[i]);
    }
    red[tid] = m;
    __syncthreads();
#pragma unroll
    for (int s = 128; s > 0; s >>= 1) {
        if (tid < s) red[tid] = fmaxf(red[tid], red[tid + s]);
        __syncthreads();
    }
    m = red[0];
    __syncthreads();

    float sum = 0.0f;
#pragma unroll
    for (int i = 0; i < 8; i++) {
        v[i] = expf(v[i] - m);
        sum += v[i];
    }
    red[tid] = sum;
    __syncthreads();
#pragma unroll
    for (int s = 128; s > 0; s >>= 1) {
        if (tid < s) red[tid] += red[tid + s];
        __syncthreads();
    }
    const float inv = 1.0f / red[0];
#pragma unroll
    for (int i = 0; i < 8; i++)
        o[i * 256 + tid] = __float2half_rn(v[i] * inv);
}

// ---------------------------------------------------------------------------
extern "C" void kernel_launch(void* const* d_in, const int* in_sizes, int n_in,
                              void* d_out, int out_size)
{
    const float* x    = (const float*)d_in[0];  // [4, 2048, 2048]
    const float* Wqkv = (const float*)d_in[1];  // [1536, 2048]
    const float* bqkv = (const float*)d_in[2];  // [1536]
    const float* Wo   = (const float*)d_in[3];  // [2048, 512]
    const float* bo   = (const float*)d_in[4];  // [2048]
    float* out = (float*)d_out;                 // [4, 2048, 2048]

    __half *xh, *wqkvh, *woh, *qkv, *ph, *ctx, *vt;
    float* attn;
    cudaGetSymbolAddress((void**)&xh,    g_xh);
    cudaGetSymbolAddress((void**)&wqkvh, g_wqkv);
    cudaGetSymbolAddress((void**)&woh,   g_wo);
    cudaGetSymbolAddress((void**)&qkv,   g_qkv);
    cudaGetSymbolAddress((void**)&attn,  g_attn);
    cudaGetSymbolAddress((void**)&ph,    g_p);
    cudaGetSymbolAddress((void**)&ctx,   g_ctx);
    cudaGetSymbolAddress((void**)&vt,    g_vt);

    cudaFuncSetAttribute(hgemm_nt<__half, true>,
                         cudaFuncAttributeMaxDynamicSharedMemorySize, GSMEM_BYTES);
    cudaFuncSetAttribute(hgemm_nt<__half, false>,
                         cudaFuncAttributeMaxDynamicSharedMemorySize, GSMEM_BYTES);
    cudaFuncSetAttribute(hgemm_nt<float, true>,
                         cudaFuncAttributeMaxDynamicSharedMemorySize, GSMEM_BYTES);
    cudaFuncSetAttribute(hgemm_nt<float, false>,
                         cudaFuncAttributeMaxDynamicSharedMemorySize, GSMEM_BYTES);

    const dim3 blk(256);
    const float inv_sqrt_d = 1.0f / sqrtf((float)Dd);

    // 0) fp32 -> fp16 conversions
    {
        const int nx = Bz * Sq * Cc;
        const int nw = QKVO * Cc;
        const int no = Cc * Dd;
        f2h_kernel<<<nx / (256 * 8), blk>>>(x, xh, nx);
        f2h_kernel<<<nw / (256 * 8), blk>>>(Wqkv, wqkvh, nw);
        f2h_kernel<<<no / (256 * 8), blk>>>(Wo, woh, no);
    }

    // 1) QKV projection: [8192,2048] x Wqkv^T + bqkv -> qkv (fp16 out)
    hgemm_nt<__half, true><<<dim3(QKVO / 128, (Bz * Sq) / 128, 1), blk, GSMEM_BYTES>>>(
        xh, Cc, 0L, wqkvh, Cc, 0L, qkv, QKVO, 0L, Cc, bqkv, 1.0f);

    // 1b) transpose V for NT PV gemm
    transpose_v<<<dim3(Sq / 32, Dd / 32, Bz), dim3(32, 8)>>>(qkv, vt);

    // 2) logits = Q K^T * (1/sqrt(d)); per batch (fp32 out)
    hgemm_nt<float, false><<<dim3(Sq / 128, Sq / 128, Bz), blk, GSMEM_BYTES>>>(
        qkv, QKVO, (long)Sq * QKVO,
        qkv + Dd, QKVO, (long)Sq * QKVO,
        attn, Sq, (long)Sq * Sq,
        Dd, nullptr, inv_sqrt_d);

    // 3) softmax: fp32 logits -> fp16 P
    softmax_kernel<<<Bz * Sq, blk>>>(attn, ph);

    // 4) ctx = P V ; per batch, NT against Vt (fp16 out)
    hgemm_nt<__half, false><<<dim3(Dd / 128, Sq / 128, Bz), blk, GSMEM_BYTES>>>(
        ph, Sq, (long)Sq * Sq,
        vt, Sq, (long)Dd * Sq,
        ctx, Dd, (long)Sq * Dd,
        Sq, nullptr, 1.0f);

    // 5) out = ctx Wo^T + bo (fp32 out)
    hgemm_nt<float, true><<<dim3(Cc / 128, (Bz * Sq) / 128, 1), blk, GSMEM_BYTES>>>(
        ctx, Dd, 0L, woh, Dd, 0L, out, Cc, 0L, Dd, bo, 1.0f);
}